// round 16
// baseline (speedup 1.0000x reference)
#include <cuda_runtime.h>
#include <math.h>

#define N_ 4
#define H_ 128
#define W_ 128
#define C_ 64
#define NET_ 32
#define HW_ (H_*W_)
#define HP_ 130
#define WP_ 130

typedef unsigned long long u64;

// -------- scratch (static device allocations; allowed) --------
__device__ float g_xen[N_*NET_*HW_];       // encoder output (NCHW)
__device__ float g_z  [N_*NET_*HW_];       // sigmoid(z)
__device__ float g_ry [N_*NET_*HW_];       // sigmoid(r) * input_y
__device__ float g_h  [N_*NET_*HW_];       // GRU state h (NCHW)
__device__ float g_y  [N_*HW_*C_];         // dw+LN+GELU output (NHWC)
__device__ float g_xpad[N_*HP_*WP_*C_];    // inp-linear output, zero-padded (NHWC)

__device__ __forceinline__ float sigmoidf_(float x){ return 1.0f/(1.0f+expf(-x)); }
__device__ __forceinline__ float siluf_(float x){ return x/(1.0f+expf(-x)); }

// ---- packed f32x2 helpers ----
__device__ __forceinline__ u64 pk2(float lo, float hi){
    u64 r; asm("mov.b64 %0,{%1,%2};" : "=l"(r) : "f"(lo), "f"(hi)); return r;
}
__device__ __forceinline__ void upk2(u64 v, float& lo, float& hi){
    asm("mov.b64 {%0,%1},%2;" : "=f"(lo), "=f"(hi) : "l"(v));
}
__device__ __forceinline__ void fma2(u64& d, u64 a, u64 b){
    asm("fma.rn.f32x2 %0,%1,%2,%0;" : "+l"(d) : "l"(a), "l"(b));
}

// ================= K1: encoder 1x1 conv + BN(eval) + SiLU =================
// grid (32, 4), block 256. Each thread: 2 consecutive pixels, all 32 outputs (packed).
__global__ void k_encoder(const float* __restrict__ x,
                          const float* __restrict__ enc_w, const float* __restrict__ enc_b,
                          const float* __restrict__ bn_g, const float* __restrict__ bn_b,
                          const float* __restrict__ bn_m, const float* __restrict__ bn_v)
{
    __shared__ u64 ws2[64*32];   // [c][o] duplicated (w,w)
    __shared__ float sc_[32], so_[32];
    int t = threadIdx.x;
    for (int i = t; i < 2048; i += 256) {
        int c = i >> 5, o = i & 31;
        float w = enc_w[o*64 + c];
        ws2[i] = pk2(w, w);
    }
    if (t < 32) {
        float s = bn_g[t] * rsqrtf(bn_v[t] + 1e-5f);
        sc_[t] = s;
        so_[t] = enc_b[t]*s + bn_b[t] - bn_m[t]*s;
    }
    __syncthreads();
    int n = blockIdx.y;
    int p0 = blockIdx.x * 512 + 2*t;
    const float* xb = x + (size_t)n*64*HW_ + p0;
    u64 acc[32];
    #pragma unroll
    for (int o = 0; o < 32; o++) acc[o] = 0ull;
    for (int c = 0; c < 64; c++) {
        u64 xv = *(const u64*)(xb + c*HW_);
        const u64* wrow = &ws2[c*32];
        #pragma unroll
        for (int o = 0; o < 32; o++) fma2(acc[o], xv, wrow[o]);
    }
    float* ob = g_xen + (size_t)n*32*HW_ + p0;
    #pragma unroll
    for (int o = 0; o < 32; o++) {
        float ax, ay; upk2(acc[o], ax, ay);
        float2 v;
        v.x = siluf_(ax*sc_[o] + so_[o]);
        v.y = siluf_(ay*sc_[o] + so_[o]);
        *(float2*)(ob + o*HW_) = v;
    }
}

// ================= K2: GRU z & r convs — f32x2 pixel-pair, reg x-window, tap-outer/o-inner =================
// grid (8,8,4), block 256. Thread: 2x2 pixels x 16 outputs (pixels packed in pairs).
__global__ void __launch_bounds__(256,2) k_gru_zr(
    const float* __restrict__ yin,
    const float* __restrict__ wz, const float* __restrict__ wr,
    const float* __restrict__ bz, const float* __restrict__ br)
{
    __shared__ float sx[8][18][18];     // 10368 B
    __shared__ u64   sw2[64][72];       // 36864 B, weights duplicated (w,w)
    __shared__ float sbias[64];
    int t = threadIdx.x;
    int og = t >> 6;                    // warp-uniform
    int pt_ = t & 63, py = pt_ >> 3, px = pt_ & 7;
    int n = blockIdx.z;
    int ty0 = blockIdx.y*16, tx0 = blockIdx.x*16;
    if (t < 64) sbias[t] = (t < 32) ? bz[t] : br[t-32];
    u64 a01[16], a23[16];               // (pix00,pix01) and (pix10,pix11)
    #pragma unroll
    for (int o = 0; o < 16; o++){ a01[o]=0ull; a23[o]=0ull; }

    for (int cc = 0; cc < 8; cc++) {
        for (int i = t; i < 2592; i += 256) {
            int ci = i / 324; int rem = i - ci*324;
            int rr = rem / 18, col = rem - rr*18;
            int gy = ty0 - 1 + rr, gx = tx0 - 1 + col;
            int cg = cc*8 + ci;
            float v = 0.f;
            if ((unsigned)gy < 128u && (unsigned)gx < 128u) {
                v = (cg < 32) ? yin[((n*32+cg)*128+gy)*128+gx]
                              : g_xen[((n*32+(cg-32))*128+gy)*128+gx];
            }
            sx[ci][rr][col] = v;
        }
        for (int i = t; i < 4608; i += 256) {
            int o = i / 72; int rem = i - o*72;
            int ci = rem / 9, tap = rem - ci*9;
            int cg = cc*8 + ci;
            float w = (o < 32) ? wz[(o*64+cg)*9+tap] : wr[((o-32)*64+cg)*9+tap];
            ((u64*)sw2)[i] = pk2(w, w);
        }
        __syncthreads();
        #pragma unroll
        for (int ci = 0; ci < 8; ci++) {
            // register x window: xr[r][c] = sx[ci][2py+r][2px+c]
            float xr[4][4];
            #pragma unroll
            for (int r = 0; r < 4; r++) {
                float2 a = *(const float2*)&sx[ci][2*py+r][2*px];
                float2 b = *(const float2*)&sx[ci][2*py+r][2*px+2];
                xr[r][0]=a.x; xr[r][1]=a.y; xr[r][2]=b.x; xr[r][3]=b.y;
            }
            // packed horizontal pairs: xp[r][s] = (xr[r][s], xr[r][s+1])
            u64 xp[4][3];
            #pragma unroll
            for (int r = 0; r < 4; r++)
                #pragma unroll
                for (int s = 0; s < 3; s++)
                    xp[r][s] = pk2(xr[r][s], xr[r][s+1]);
            #pragma unroll
            for (int tap = 0; tap < 9; tap++) {
                const int ky = tap/3, kx = tap%3;
                u64 xa = xp[ky  ][kx];
                u64 xb = xp[ky+1][kx];
                #pragma unroll
                for (int o = 0; o < 16; o++) {
                    u64 w2 = sw2[og*16+o][ci*9+tap];
                    fma2(a01[o], xa, w2);
                    fma2(a23[o], xb, w2);
                }
            }
        }
        __syncthreads();
    }
    #pragma unroll
    for (int o = 0; o < 16; o++) {
        int oc = og*16 + o;
        float v00, v01, v10, v11;
        upk2(a01[o], v00, v01);
        upk2(a23[o], v10, v11);
        float vq[4] = {v00, v01, v10, v11};
        #pragma unroll
        for (int q = 0; q < 4; q++) {
            int gy = ty0 + 2*py + (q>>1), gx = tx0 + 2*px + (q&1);
            float v = vq[q] + sbias[oc];
            if (oc < 32) {
                g_z[((n*32+oc)*128+gy)*128+gx] = sigmoidf_(v);
            } else {
                int rc = oc - 32;
                int idx = ((n*32+rc)*128+gy)*128+gx;
                g_ry[idx] = sigmoidf_(v) * yin[idx];
            }
        }
    }
}

// ================= K3: GRU q conv + h update — same f32x2 structure =================
// grid (8,8,4), block 256. Thread: 2x2 pixels x 8 outputs.
__global__ void __launch_bounds__(256,2) k_gru_q(
    const float* __restrict__ yin,
    const float* __restrict__ wq, const float* __restrict__ bq,
    float* __restrict__ hout2)
{
    __shared__ float sx[8][18][18];
    __shared__ u64   sw2[32][72];       // 18432 B
    __shared__ float sbias[32];
    int t = threadIdx.x;
    int og = t >> 6;
    int pt_ = t & 63, py = pt_ >> 3, px = pt_ & 7;
    int n = blockIdx.z;
    int ty0 = blockIdx.y*16, tx0 = blockIdx.x*16;
    if (t < 32) sbias[t] = bq[t];
    u64 a01[8], a23[8];
    #pragma unroll
    for (int o = 0; o < 8; o++){ a01[o]=0ull; a23[o]=0ull; }

    for (int cc = 0; cc < 8; cc++) {
        for (int i = t; i < 2592; i += 256) {
            int ci = i / 324; int rem = i - ci*324;
            int rr = rem / 18, col = rem - rr*18;
            int gy = ty0 - 1 + rr, gx = tx0 - 1 + col;
            int cg = cc*8 + ci;
            float v = 0.f;
            if ((unsigned)gy < 128u && (unsigned)gx < 128u) {
                v = (cg < 32) ? g_ry[((n*32+cg)*128+gy)*128+gx]
                              : g_xen[((n*32+(cg-32))*128+gy)*128+gx];
            }
            sx[ci][rr][col] = v;
        }
        for (int i = t; i < 2304; i += 256) {
            int o = i / 72; int rem = i - o*72;
            int ci = rem / 9, tap = rem - ci*9;
            int cg = cc*8 + ci;
            float w = wq[(o*64+cg)*9+tap];
            ((u64*)sw2)[i] = pk2(w, w);
        }
        __syncthreads();
        #pragma unroll
        for (int ci = 0; ci < 8; ci++) {
            float xr[4][4];
            #pragma unroll
            for (int r = 0; r < 4; r++) {
                float2 a = *(const float2*)&sx[ci][2*py+r][2*px];
                float2 b = *(const float2*)&sx[ci][2*py+r][2*px+2];
                xr[r][0]=a.x; xr[r][1]=a.y; xr[r][2]=b.x; xr[r][3]=b.y;
            }
            u64 xp[4][3];
            #pragma unroll
            for (int r = 0; r < 4; r++)
                #pragma unroll
                for (int s = 0; s < 3; s++)
                    xp[r][s] = pk2(xr[r][s], xr[r][s+1]);
            #pragma unroll
            for (int tap = 0; tap < 9; tap++) {
                const int ky = tap/3, kx = tap%3;
                u64 xa = xp[ky  ][kx];
                u64 xb = xp[ky+1][kx];
                #pragma unroll
                for (int o = 0; o < 8; o++) {
                    u64 w2 = sw2[og*8+o][ci*9+tap];
                    fma2(a01[o], xa, w2);
                    fma2(a23[o], xb, w2);
                }
            }
        }
        __syncthreads();
    }
    #pragma unroll
    for (int o = 0; o < 8; o++) {
        int oc = og*8 + o;
        float v00, v01, v10, v11;
        upk2(a01[o], v00, v01);
        upk2(a23[o], v10, v11);
        float vq[4] = {v00, v01, v10, v11};
        #pragma unroll
        for (int q = 0; q < 4; q++) {
            int gy = ty0 + 2*py + (q>>1), gx = tx0 + 2*px + (q&1);
            int idx = ((n*32+oc)*128+gy)*128+gx;
            float qq = tanhf(vq[q] + sbias[oc]);
            float z  = g_z[idx];
            float yv = yin[idx];
            float hh = (1.f - z)*yv + z*qq;
            g_h[idx] = hh;
            if (hout2) hout2[idx] = hh;
        }
    }
}

// ================= K4: inp 1x1 linear -> zero-padded NHWC, f32x2, 4-way out split =================
// grid (33, 4, 4), block 256. blockIdx.y = output quarter (16 ch). Thread: 2 pixels x 16 outs.
__global__ void k_inp(const float* __restrict__ x,
                      const float* __restrict__ inp_w, const float* __restrict__ inp_b)
{
    __shared__ u64 ws2[64*16];
    __shared__ float bsh[16];
    int t = threadIdx.x;
    int og = blockIdx.y, n = blockIdx.z;

    if (blockIdx.x == 32) {   // border zero
        for (int i = t; i < 516; i += 256) {
            int row, col;
            if (i < 130)      { row = 0;        col = i; }
            else if (i < 260) { row = 129;      col = i-130; }
            else if (i < 388) { row = i-260+1;  col = 0; }
            else              { row = i-388+1;  col = 129; }
            float* dst = g_xpad + (((size_t)n*HP_ + row)*WP_ + col)*64 + og*16;
            #pragma unroll
            for (int o = 0; o < 16; o += 4)
                *(float4*)(dst+o) = make_float4(0.f,0.f,0.f,0.f);
        }
        return;
    }

    for (int i = t; i < 1024; i += 256) {
        int c = i >> 4, o = i & 15;
        float w = inp_w[(og*16+o)*64 + c];
        ws2[i] = pk2(w, w);
    }
    if (t < 16) bsh[t] = inp_b[og*16 + t];
    __syncthreads();

    int pix0 = blockIdx.x*512 + 2*t;
    int h = pix0 >> 7, w0 = pix0 & 127;
    const float* xb = x + (size_t)n*64*HW_ + pix0;
    u64 acc[16];
    #pragma unroll
    for (int o = 0; o < 16; o++) acc[o] = pk2(bsh[o], bsh[o]);
    for (int c = 0; c < 64; c++) {
        u64 xv = *(const u64*)(xb + c*HW_);
        const u64* wrow = &ws2[c*16];
        #pragma unroll
        for (int o = 0; o < 16; o++) fma2(acc[o], xv, wrow[o]);
    }
    float r0[16], r1[16];
    #pragma unroll
    for (int o = 0; o < 16; o++) upk2(acc[o], r0[o], r1[o]);
    float* dst = g_xpad + (((size_t)n*HP_ + (h+1))*WP_ + (w0+1))*64 + og*16;
    #pragma unroll
    for (int o = 0; o < 16; o += 4) {
        *(float4*)(dst + o)      = make_float4(r0[o], r0[o+1], r0[o+2], r0[o+3]);
        *(float4*)(dst + 64 + o) = make_float4(r1[o], r1[o+1], r1[o+2], r1[o+3]);
    }
}

// ================= K5: depthwise conv(groups=32, 32->64) + LN + GELU =================
// grid (8,8,4), block 256. Thread: one pixel, all 64 channels.
__global__ void k_dwln(const float* __restrict__ dw_w, const float* __restrict__ dw_b,
                       const float* __restrict__ ln_g, const float* __restrict__ ln_b)
{
    __shared__ float sh_[32][18][18];
    __shared__ float sw[576];
    __shared__ float sb[64], sg[64], sbb[64];
    int t = threadIdx.x;
    int n = blockIdx.z;
    int ty0 = blockIdx.y*16, tx0 = blockIdx.x*16;
    for (int i = t; i < 32*324; i += 256) {
        int ci = i / 324; int rem = i - ci*324;
        int rr = rem / 18, col = rem - rr*18;
        int gy = ty0 - 1 + rr, gx = tx0 - 1 + col;
        float v = 0.f;
        if ((unsigned)gy < 128u && (unsigned)gx < 128u)
            v = g_h[((n*32+ci)*128+gy)*128+gx];
        sh_[ci][rr][col] = v;
    }
    for (int i = t; i < 576; i += 256) sw[i] = dw_w[i];
    if (t < 64) { sb[t]=dw_b[t]; sg[t]=ln_g[t]; sbb[t]=ln_b[t]; }
    __syncthreads();
    int ty = t >> 4, tx = t & 15;
    float v[64];
    #pragma unroll
    for (int c = 0; c < 32; c++) {
        float a0 = 0.f, a1 = 0.f;
        #pragma unroll
        for (int tap = 0; tap < 9; tap++) {
            int ky = tap/3, kx = tap%3;
            float xv = sh_[c][ty+ky][tx+kx];
            a0 += xv * sw[(2*c  )*9 + tap];
            a1 += xv * sw[(2*c+1)*9 + tap];
        }
        v[2*c]   = a0 + sb[2*c];
        v[2*c+1] = a1 + sb[2*c+1];
    }
    float mu = 0.f;
    #pragma unroll
    for (int c = 0; c < 64; c++) mu += v[c];
    mu *= (1.0f/64.0f);
    float var = 0.f;
    #pragma unroll
    for (int c = 0; c < 64; c++) { float d = v[c]-mu; var += d*d; }
    var *= (1.0f/64.0f);
    float inv = rsqrtf(var + 1e-6f);
    float* dst = g_y + (((size_t)n*128 + ty0+ty)*128 + tx0+tx)*64;
    #pragma unroll
    for (int c = 0; c < 64; c += 4) {
        float4 o4;
        float* po = (float*)&o4;
        #pragma unroll
        for (int j = 0; j < 4; j++) {
            float yv = (v[c+j]-mu)*inv*sg[c+j] + sbb[c+j];
            po[j] = 0.5f*yv*(1.0f + erff(yv*0.70710678118654752f));
        }
        *(float4*)(dst + c) = o4;
    }
}

// ================= K6: fused dcn — transposed staging + f32x2 phases 1/3 =================
// grid (8, 128, 4), block 512. Block: 16 consecutive pixels of one row.
__global__ void __launch_bounds__(512) k_dcn(
    const float* __restrict__ off_w, const float* __restrict__ off_b,
    const float* __restrict__ mask_w, const float* __restrict__ mask_b,
    const float* __restrict__ out_w, const float* __restrict__ out_b,
    float* __restrict__ out)
{
    __shared__ __align__(16) float y_sT[64][18];   // [c][p], padded
    __shared__ float wT[64][112];     // phase1: off+mask transposed; phase3: out_w transposed
    __shared__ float b_om[108];
    __shared__ float om[16][112];     // per-pixel: offset[0:72], mask[72:108]; reused as out-staging
    __shared__ __align__(16) float val_sT[64][18]; // [c][p]
    int t = threadIdx.x;
    int n = blockIdx.z, h = blockIdx.y, w0 = blockIdx.x*16;

    {   // load y tile transposed
        const float* src = g_y + (((size_t)n*128 + h)*128 + w0)*64;
        for (int i = t; i < 1024; i += 512) {
            int p = i >> 6, c = i & 63;
            y_sT[c][p] = src[i];
        }
    }
    for (int i = t; i < 6912; i += 512) {       // off_w + mask_w, transposed
        int k = i >> 6, c = i & 63;
        wT[c][k] = (k < 72) ? off_w[k*64+c] : mask_w[(k-72)*64+c];
    }
    if (t < 108) b_om[t] = (t < 72) ? off_b[t] : mask_b[t-72];
    __syncthreads();

    // ---- phase 1: offset + mask logits (108 outputs x 16 pixels), f32x2 pixel pairs ----
    {
        int o = t & 127, pg = t >> 7;           // pg warp-uniform (0..3), 4 pixels each
        if (o < 108) {
            float b = b_om[o];
            u64 a01 = pk2(b, b), a23 = pk2(b, b);
            for (int c = 0; c < 64; c++) {
                float wv = wT[c][o];
                u64 w2 = pk2(wv, wv);
                u64 ya = *(const u64*)&y_sT[c][pg*4];     // broadcast
                u64 yb = *(const u64*)&y_sT[c][pg*4+2];   // broadcast
                fma2(a01, ya, w2);
                fma2(a23, yb, w2);
            }
            float v0,v1,v2,v3;
            upk2(a01, v0, v1); upk2(a23, v2, v3);
            om[pg*4+0][o] = v0; om[pg*4+1][o] = v1;
            om[pg*4+2][o] = v2; om[pg*4+3][o] = v3;
        }
    }
    __syncthreads();

    // reload wT with out_w transposed (used in phase 3)
    for (int i = t; i < 4096; i += 512) {
        int o = i >> 6, c = i & 63;
        wT[c][o] = out_w[o*64+c];
    }
    // softmax over P=9 per (pixel, group)
    if (t < 64) {
        int p = t >> 2, g = t & 3;
        float* m = &om[p][72 + g*9];
        float mx = m[0];
        #pragma unroll
        for (int i = 1; i < 9; i++) mx = fmaxf(mx, m[i]);
        float e[9]; float s = 0.f;
        #pragma unroll
        for (int i = 0; i < 9; i++){ e[i] = expf(m[i]-mx); s += e[i]; }
        float inv = 1.0f/s;
        #pragma unroll
        for (int i = 0; i < 9; i++) m[i] = e[i]*inv;
    }
    __syncthreads();

    // ---- phase 2: bilinear sampling. warp = pixel, lane -> (group, channel pair) ----
    {
        int p = t >> 5, l = t & 31;
        int g = l >> 3;
        int wg = w0 + p;
        float v0 = 0.f, v1 = 0.f;
        const float* xb = g_xpad + (size_t)n*HP_*WP_*64 + 2*l;   // channels 2l, 2l+1
        #pragma unroll
        for (int pt = 0; pt < 9; pt++) {
            float ox = om[p][(g*9+pt)*2+0];
            float oy = om[p][(g*9+pt)*2+1];
            float mm = om[p][72 + g*9 + pt];
            float fx = (float)(wg + (pt/3)) + ox;
            float fy = (float)(h  + (pt%3)) + oy;
            float fx0 = floorf(fx), fy0 = floorf(fy);
            int ix0 = (int)fx0, iy0 = (int)fy0;
            float wx1 = fx - fx0, wy1 = fy - fy0;
            float wx0 = 1.f - wx1, wy0 = 1.f - wy1;
            #pragma unroll
            for (int cr = 0; cr < 4; cr++) {
                int ix = ix0 + (cr & 1), iy = iy0 + (cr >> 1);
                float wgt = ((cr&1) ? wx1 : wx0) * ((cr>>1) ? wy1 : wy0) * mm;
                if ((unsigned)ix < (unsigned)WP_ && (unsigned)iy < (unsigned)HP_) {
                    float2 xv = *(const float2*)(xb + ((size_t)iy*WP_ + ix)*64);
                    v0 += wgt*xv.x; v1 += wgt*xv.y;
                }
            }
        }
        val_sT[2*l  ][p] = v0;   // 2 STS per thread; conflict cost negligible
        val_sT[2*l+1][p] = v1;
    }
    __syncthreads();

    // ---- phase 3: out linear + SiLU, f32x2 pixel pairs ----
    float* ostage = &om[0][0];
    {
        int o = t & 63, pg = t >> 6;            // pg warp-uniform (0..7), 2 pixels each
        float b = out_b[o];
        u64 a = pk2(b, b);
        for (int c = 0; c < 64; c++) {
            float wv = wT[c][o];
            u64 w2 = pk2(wv, wv);
            u64 vv = *(const u64*)&val_sT[c][pg*2];      // broadcast
            fma2(a, vv, w2);
        }
        float a0, a1; upk2(a, a0, a1);
        ostage[o*16 + pg*2+0] = siluf_(a0);
        ostage[o*16 + pg*2+1] = siluf_(a1);
    }
    __syncthreads();
    for (int i = t; i < 1024; i += 512) {
        int o = i >> 4, pw = i & 15;
        out[((size_t)(n*64+o)*128 + h)*128 + w0 + pw] = ostage[i];
    }
}

// ================= launch =================
extern "C" void kernel_launch(void* const* d_in, const int* in_sizes, int n_in,
                              void* d_out, int out_size)
{
    const float* input_x = (const float*)d_in[0];
    const float* input_y = (const float*)d_in[1];
    const float* enc_w   = (const float*)d_in[2];
    const float* enc_b   = (const float*)d_in[3];
    const float* bn_g    = (const float*)d_in[4];
    const float* bn_b    = (const float*)d_in[5];
    const float* bn_m    = (const float*)d_in[6];
    const float* bn_v    = (const float*)d_in[7];
    const float* gru_wz  = (const float*)d_in[8];
    const float* gru_bz  = (const float*)d_in[9];
    const float* gru_wr  = (const float*)d_in[10];
    const float* gru_br  = (const float*)d_in[11];
    const float* gru_wq  = (const float*)d_in[12];
    const float* gru_bq  = (const float*)d_in[13];
    const float* dw_w    = (const float*)d_in[14];
    const float* dw_b    = (const float*)d_in[15];
    const float* ln_g    = (const float*)d_in[16];
    const float* ln_b    = (const float*)d_in[17];
    const float* off_w   = (const float*)d_in[18];
    const float* off_b   = (const float*)d_in[19];
    const float* mask_w  = (const float*)d_in[20];
    const float* mask_b  = (const float*)d_in[21];
    const float* inp_w   = (const float*)d_in[22];
    const float* inp_b   = (const float*)d_in[23];
    const float* out_w   = (const float*)d_in[24];
    const float* out_b   = (const float*)d_in[25];

    float* out = (float*)d_out;
    const int OUT1 = N_*C_*HW_;          // 4194304
    const int OUT2 = N_*NET_*HW_;        // 2097152
    float* h_out = (out_size >= OUT1 + OUT2) ? (out + OUT1) : nullptr;

    k_encoder<<<dim3(32,4),   256>>>(input_x, enc_w, enc_b, bn_g, bn_b, bn_m, bn_v);
    k_gru_zr <<<dim3(8,8,4),  256>>>(input_y, gru_wz, gru_wr, gru_bz, gru_br);
    k_gru_q  <<<dim3(8,8,4),  256>>>(input_y, gru_wq, gru_bq, h_out);
    k_inp    <<<dim3(33,4,4), 256>>>(input_x, inp_w, inp_b);
    k_dwln   <<<dim3(8,8,4),  256>>>(dw_w, dw_b, ln_g, ln_b);
    k_dcn    <<<dim3(8,128,4),512>>>(off_w, off_b, mask_w, mask_b, out_w, out_b, out);
}

// round 17
// speedup vs baseline: 1.0143x; 1.0143x over previous
#include <cuda_runtime.h>
#include <math.h>

#define N_ 4
#define H_ 128
#define W_ 128
#define C_ 64
#define NET_ 32
#define HW_ (H_*W_)
#define HP_ 130
#define WP_ 130

typedef unsigned long long u64;

// -------- scratch (static device allocations; allowed) --------
__device__ float g_xen[N_*NET_*HW_];       // encoder output (NCHW)
__device__ float g_z  [N_*NET_*HW_];       // sigmoid(z)
__device__ float g_ry [N_*NET_*HW_];       // sigmoid(r) * input_y
__device__ float g_h  [N_*NET_*HW_];       // GRU state h (NCHW)
__device__ float g_y  [N_*HW_*C_];         // dw+LN+GELU output (NHWC)
__device__ float g_xpad[N_*HP_*WP_*C_];    // inp-linear output, zero-padded (NHWC)

__device__ __forceinline__ float sigmoidf_(float x){ return 1.0f/(1.0f+expf(-x)); }
__device__ __forceinline__ float siluf_(float x){ return x/(1.0f+expf(-x)); }

// ---- packed f32x2 helpers ----
__device__ __forceinline__ u64 pk2(float lo, float hi){
    u64 r; asm("mov.b64 %0,{%1,%2};" : "=l"(r) : "f"(lo), "f"(hi)); return r;
}
__device__ __forceinline__ void upk2(u64 v, float& lo, float& hi){
    asm("mov.b64 {%0,%1},%2;" : "=f"(lo), "=f"(hi) : "l"(v));
}
__device__ __forceinline__ void fma2(u64& d, u64 a, u64 b){
    asm("fma.rn.f32x2 %0,%1,%2,%0;" : "+l"(d) : "l"(a), "l"(b));
}
__device__ __forceinline__ float lo2(u64 v){ float a,b; upk2(v,a,b); return a; }
__device__ __forceinline__ float hi2(u64 v){ float a,b; upk2(v,a,b); return b; }

// ================= K1: encoder 1x1 conv + BN(eval) + SiLU =================
__global__ void k_encoder(const float* __restrict__ x,
                          const float* __restrict__ enc_w, const float* __restrict__ enc_b,
                          const float* __restrict__ bn_g, const float* __restrict__ bn_b,
                          const float* __restrict__ bn_m, const float* __restrict__ bn_v)
{
    __shared__ u64 ws2[64*32];   // [c][o] duplicated (w,w)
    __shared__ float sc_[32], so_[32];
    int t = threadIdx.x;
    for (int i = t; i < 2048; i += 256) {
        int c = i >> 5, o = i & 31;
        float w = enc_w[o*64 + c];
        ws2[i] = pk2(w, w);
    }
    if (t < 32) {
        float s = bn_g[t] * rsqrtf(bn_v[t] + 1e-5f);
        sc_[t] = s;
        so_[t] = enc_b[t]*s + bn_b[t] - bn_m[t]*s;
    }
    __syncthreads();
    int n = blockIdx.y;
    int p0 = blockIdx.x * 512 + 2*t;
    const float* xb = x + (size_t)n*64*HW_ + p0;
    u64 acc[32];
    #pragma unroll
    for (int o = 0; o < 32; o++) acc[o] = 0ull;
    for (int c = 0; c < 64; c++) {
        u64 xv = *(const u64*)(xb + c*HW_);
        const u64* wrow = &ws2[c*32];
        #pragma unroll
        for (int o = 0; o < 32; o++) fma2(acc[o], xv, wrow[o]);
    }
    float* ob = g_xen + (size_t)n*32*HW_ + p0;
    #pragma unroll
    for (int o = 0; o < 32; o++) {
        float ax, ay; upk2(acc[o], ax, ay);
        float2 v;
        v.x = siluf_(ax*sc_[o] + so_[o]);
        v.y = siluf_(ay*sc_[o] + so_[o]);
        *(float2*)(ob + o*HW_) = v;
    }
}

// ================= K2: GRU z & r convs — f32x2, direct-packed x pairs (reg-trimmed) =================
// grid (8,8,4), block 256. Thread: 2x2 pixels x 16 outputs (pixels packed in pairs).
__global__ void __launch_bounds__(256,2) k_gru_zr(
    const float* __restrict__ yin,
    const float* __restrict__ wz, const float* __restrict__ wr,
    const float* __restrict__ bz, const float* __restrict__ br)
{
    __shared__ float sx[8][18][18];     // 10368 B
    __shared__ u64   sw2[64][72];       // 36864 B, weights duplicated (w,w)
    __shared__ float sbias[64];
    int t = threadIdx.x;
    int og = t >> 6;                    // warp-uniform
    int pt_ = t & 63, py = pt_ >> 3, px = pt_ & 7;
    int n = blockIdx.z;
    int ty0 = blockIdx.y*16, tx0 = blockIdx.x*16;
    if (t < 64) sbias[t] = (t < 32) ? bz[t] : br[t-32];
    u64 a01[16], a23[16];               // (pix00,pix01) and (pix10,pix11)
    #pragma unroll
    for (int o = 0; o < 16; o++){ a01[o]=0ull; a23[o]=0ull; }

    for (int cc = 0; cc < 8; cc++) {
        for (int i = t; i < 2592; i += 256) {
            int ci = i / 324; int rem = i - ci*324;
            int rr = rem / 18, col = rem - rr*18;
            int gy = ty0 - 1 + rr, gx = tx0 - 1 + col;
            int cg = cc*8 + ci;
            float v = 0.f;
            if ((unsigned)gy < 128u && (unsigned)gx < 128u) {
                v = (cg < 32) ? yin[((n*32+cg)*128+gy)*128+gx]
                              : g_xen[((n*32+(cg-32))*128+gy)*128+gx];
            }
            sx[ci][rr][col] = v;
        }
        for (int i = t; i < 4608; i += 256) {
            int o = i / 72; int rem = i - o*72;
            int ci = rem / 9, tap = rem - ci*9;
            int cg = cc*8 + ci;
            float w = (o < 32) ? wz[(o*64+cg)*9+tap] : wr[((o-32)*64+cg)*9+tap];
            ((u64*)sw2)[i] = pk2(w, w);
        }
        __syncthreads();
        #pragma unroll
        for (int ci = 0; ci < 8; ci++) {
            // packed pairs directly from smem: xp[r][0]=(x0,x1), xp[r][2]=(x2,x3) are
            // aligned LDS.64; xp[r][1]=(x1,x2) is one cross-pack.
            u64 xp[4][3];
            #pragma unroll
            for (int r = 0; r < 4; r++) {
                u64 A = *(const u64*)&sx[ci][2*py+r][2*px];
                u64 B = *(const u64*)&sx[ci][2*py+r][2*px+2];
                xp[r][0] = A;
                xp[r][2] = B;
                xp[r][1] = pk2(hi2(A), lo2(B));
            }
            #pragma unroll
            for (int tap = 0; tap < 9; tap++) {
                const int ky = tap/3, kx = tap%3;
                u64 xa = xp[ky  ][kx];
                u64 xb = xp[ky+1][kx];
                #pragma unroll
                for (int o = 0; o < 16; o++) {
                    u64 w2 = sw2[og*16+o][ci*9+tap];
                    fma2(a01[o], xa, w2);
                    fma2(a23[o], xb, w2);
                }
            }
        }
        __syncthreads();
    }
    #pragma unroll
    for (int o = 0; o < 16; o++) {
        int oc = og*16 + o;
        float v00, v01, v10, v11;
        upk2(a01[o], v00, v01);
        upk2(a23[o], v10, v11);
        float vq[4] = {v00, v01, v10, v11};
        #pragma unroll
        for (int q = 0; q < 4; q++) {
            int gy = ty0 + 2*py + (q>>1), gx = tx0 + 2*px + (q&1);
            float v = vq[q] + sbias[oc];
            if (oc < 32) {
                g_z[((n*32+oc)*128+gy)*128+gx] = sigmoidf_(v);
            } else {
                int rc = oc - 32;
                int idx = ((n*32+rc)*128+gy)*128+gx;
                g_ry[idx] = sigmoidf_(v) * yin[idx];
            }
        }
    }
}

// ================= K3: GRU q conv + h update — same structure =================
__global__ void __launch_bounds__(256,2) k_gru_q(
    const float* __restrict__ yin,
    const float* __restrict__ wq, const float* __restrict__ bq,
    float* __restrict__ hout2)
{
    __shared__ float sx[8][18][18];
    __shared__ u64   sw2[32][72];       // 18432 B
    __shared__ float sbias[32];
    int t = threadIdx.x;
    int og = t >> 6;
    int pt_ = t & 63, py = pt_ >> 3, px = pt_ & 7;
    int n = blockIdx.z;
    int ty0 = blockIdx.y*16, tx0 = blockIdx.x*16;
    if (t < 32) sbias[t] = bq[t];
    u64 a01[8], a23[8];
    #pragma unroll
    for (int o = 0; o < 8; o++){ a01[o]=0ull; a23[o]=0ull; }

    for (int cc = 0; cc < 8; cc++) {
        for (int i = t; i < 2592; i += 256) {
            int ci = i / 324; int rem = i - ci*324;
            int rr = rem / 18, col = rem - rr*18;
            int gy = ty0 - 1 + rr, gx = tx0 - 1 + col;
            int cg = cc*8 + ci;
            float v = 0.f;
            if ((unsigned)gy < 128u && (unsigned)gx < 128u) {
                v = (cg < 32) ? g_ry[((n*32+cg)*128+gy)*128+gx]
                              : g_xen[((n*32+(cg-32))*128+gy)*128+gx];
            }
            sx[ci][rr][col] = v;
        }
        for (int i = t; i < 2304; i += 256) {
            int o = i / 72; int rem = i - o*72;
            int ci = rem / 9, tap = rem - ci*9;
            int cg = cc*8 + ci;
            float w = wq[(o*64+cg)*9+tap];
            ((u64*)sw2)[i] = pk2(w, w);
        }
        __syncthreads();
        #pragma unroll
        for (int ci = 0; ci < 8; ci++) {
            u64 xp[4][3];
            #pragma unroll
            for (int r = 0; r < 4; r++) {
                u64 A = *(const u64*)&sx[ci][2*py+r][2*px];
                u64 B = *(const u64*)&sx[ci][2*py+r][2*px+2];
                xp[r][0] = A;
                xp[r][2] = B;
                xp[r][1] = pk2(hi2(A), lo2(B));
            }
            #pragma unroll
            for (int tap = 0; tap < 9; tap++) {
                const int ky = tap/3, kx = tap%3;
                u64 xa = xp[ky  ][kx];
                u64 xb = xp[ky+1][kx];
                #pragma unroll
                for (int o = 0; o < 8; o++) {
                    u64 w2 = sw2[og*8+o][ci*9+tap];
                    fma2(a01[o], xa, w2);
                    fma2(a23[o], xb, w2);
                }
            }
        }
        __syncthreads();
    }
    #pragma unroll
    for (int o = 0; o < 8; o++) {
        int oc = og*8 + o;
        float v00, v01, v10, v11;
        upk2(a01[o], v00, v01);
        upk2(a23[o], v10, v11);
        float vq[4] = {v00, v01, v10, v11};
        #pragma unroll
        for (int q = 0; q < 4; q++) {
            int gy = ty0 + 2*py + (q>>1), gx = tx0 + 2*px + (q&1);
            int idx = ((n*32+oc)*128+gy)*128+gx;
            float qq = tanhf(vq[q] + sbias[oc]);
            float z  = g_z[idx];
            float yv = yin[idx];
            float hh = (1.f - z)*yv + z*qq;
            g_h[idx] = hh;
            if (hout2) hout2[idx] = hh;
        }
    }
}

// ================= K4: inp 1x1 linear -> zero-padded NHWC — 4 pixels/thread =================
// grid (17, 4, 4), block 256. blockIdx.y = output quarter (16 ch). Thread: 4 pixels x 16 outs.
// blockIdx.x == 16 zeroes the pad border.
__global__ void k_inp(const float* __restrict__ x,
                      const float* __restrict__ inp_w, const float* __restrict__ inp_b)
{
    __shared__ u64 ws2[64*16];
    __shared__ float bsh[16];
    int t = threadIdx.x;
    int og = blockIdx.y, n = blockIdx.z;

    if (blockIdx.x == 16) {   // border zero
        for (int i = t; i < 516; i += 256) {
            int row, col;
            if (i < 130)      { row = 0;        col = i; }
            else if (i < 260) { row = 129;      col = i-130; }
            else if (i < 388) { row = i-260+1;  col = 0; }
            else              { row = i-388+1;  col = 129; }
            float* dst = g_xpad + (((size_t)n*HP_ + row)*WP_ + col)*64 + og*16;
            #pragma unroll
            for (int o = 0; o < 16; o += 4)
                *(float4*)(dst+o) = make_float4(0.f,0.f,0.f,0.f);
        }
        return;
    }

    for (int i = t; i < 1024; i += 256) {
        int c = i >> 4, o = i & 15;
        float w = inp_w[(og*16+o)*64 + c];
        ws2[i] = pk2(w, w);
    }
    if (t < 16) bsh[t] = inp_b[og*16 + t];
    __syncthreads();

    int pix0 = blockIdx.x*1024 + 4*t;          // 4 consecutive pixels
    const float* xb = x + (size_t)n*64*HW_ + pix0;
    u64 accA[16], accB[16];
    #pragma unroll
    for (int o = 0; o < 16; o++) { accA[o] = pk2(bsh[o], bsh[o]); accB[o] = accA[o]; }
    for (int c = 0; c < 64; c++) {
        u64 xa = *(const u64*)(xb + c*HW_);
        u64 xbv = *(const u64*)(xb + c*HW_ + 2);
        const u64* wrow = &ws2[c*16];
        #pragma unroll
        for (int o = 0; o < 16; o++) { fma2(accA[o], xa, wrow[o]); fma2(accB[o], xbv, wrow[o]); }
    }
    int h = pix0 >> 7, w0 = pix0 & 127;
    float* dst = g_xpad + (((size_t)n*HP_ + (h+1))*WP_ + (w0+1))*64 + og*16;
    float rA0[16], rA1[16], rB0[16], rB1[16];
    #pragma unroll
    for (int o = 0; o < 16; o++) { upk2(accA[o], rA0[o], rA1[o]); upk2(accB[o], rB0[o], rB1[o]); }
    #pragma unroll
    for (int o = 0; o < 16; o += 4) {
        *(float4*)(dst + o)        = make_float4(rA0[o], rA0[o+1], rA0[o+2], rA0[o+3]);
        *(float4*)(dst + 64 + o)   = make_float4(rA1[o], rA1[o+1], rA1[o+2], rA1[o+3]);
        *(float4*)(dst + 128 + o)  = make_float4(rB0[o], rB0[o+1], rB0[o+2], rB0[o+3]);
        *(float4*)(dst + 192 + o)  = make_float4(rB1[o], rB1[o+1], rB1[o+2], rB1[o+3]);
    }
}

// ================= K5: depthwise conv(groups=32, 32->64) + LN + GELU =================
__global__ void k_dwln(const float* __restrict__ dw_w, const float* __restrict__ dw_b,
                       const float* __restrict__ ln_g, const float* __restrict__ ln_b)
{
    __shared__ float sh_[32][18][18];
    __shared__ float sw[576];
    __shared__ float sb[64], sg[64], sbb[64];
    int t = threadIdx.x;
    int n = blockIdx.z;
    int ty0 = blockIdx.y*16, tx0 = blockIdx.x*16;
    for (int i = t; i < 32*324; i += 256) {
        int ci = i / 324; int rem = i - ci*324;
        int rr = rem / 18, col = rem - rr*18;
        int gy = ty0 - 1 + rr, gx = tx0 - 1 + col;
        float v = 0.f;
        if ((unsigned)gy < 128u && (unsigned)gx < 128u)
            v = g_h[((n*32+ci)*128+gy)*128+gx];
        sh_[ci][rr][col] = v;
    }
    for (int i = t; i < 576; i += 256) sw[i] = dw_w[i];
    if (t < 64) { sb[t]=dw_b[t]; sg[t]=ln_g[t]; sbb[t]=ln_b[t]; }
    __syncthreads();
    int ty = t >> 4, tx = t & 15;
    float v[64];
    #pragma unroll
    for (int c = 0; c < 32; c++) {
        float a0 = 0.f, a1 = 0.f;
        #pragma unroll
        for (int tap = 0; tap < 9; tap++) {
            int ky = tap/3, kx = tap%3;
            float xv = sh_[c][ty+ky][tx+kx];
            a0 += xv * sw[(2*c  )*9 + tap];
            a1 += xv * sw[(2*c+1)*9 + tap];
        }
        v[2*c]   = a0 + sb[2*c];
        v[2*c+1] = a1 + sb[2*c+1];
    }
    float mu = 0.f;
    #pragma unroll
    for (int c = 0; c < 64; c++) mu += v[c];
    mu *= (1.0f/64.0f);
    float var = 0.f;
    #pragma unroll
    for (int c = 0; c < 64; c++) { float d = v[c]-mu; var += d*d; }
    var *= (1.0f/64.0f);
    float inv = rsqrtf(var + 1e-6f);
    float* dst = g_y + (((size_t)n*128 + ty0+ty)*128 + tx0+tx)*64;
    #pragma unroll
    for (int c = 0; c < 64; c += 4) {
        float4 o4;
        float* po = (float*)&o4;
        #pragma unroll
        for (int j = 0; j < 4; j++) {
            float yv = (v[c+j]-mu)*inv*sg[c+j] + sbb[c+j];
            po[j] = 0.5f*yv*(1.0f + erff(yv*0.70710678118654752f));
        }
        *(float4*)(dst + c) = o4;
    }
}

// ================= K6: fused dcn — transposed staging + f32x2 phases 1/3 =================
__global__ void __launch_bounds__(512) k_dcn(
    const float* __restrict__ off_w, const float* __restrict__ off_b,
    const float* __restrict__ mask_w, const float* __restrict__ mask_b,
    const float* __restrict__ out_w, const float* __restrict__ out_b,
    float* __restrict__ out)
{
    __shared__ __align__(16) float y_sT[64][18];   // [c][p], padded
    __shared__ float wT[64][112];
    __shared__ float b_om[108];
    __shared__ float om[16][112];
    __shared__ __align__(16) float val_sT[64][18];
    int t = threadIdx.x;
    int n = blockIdx.z, h = blockIdx.y, w0 = blockIdx.x*16;

    {
        const float* src = g_y + (((size_t)n*128 + h)*128 + w0)*64;
        for (int i = t; i < 1024; i += 512) {
            int p = i >> 6, c = i & 63;
            y_sT[c][p] = src[i];
        }
    }
    for (int i = t; i < 6912; i += 512) {
        int k = i >> 6, c = i & 63;
        wT[c][k] = (k < 72) ? off_w[k*64+c] : mask_w[(k-72)*64+c];
    }
    if (t < 108) b_om[t] = (t < 72) ? off_b[t] : mask_b[t-72];
    __syncthreads();

    {
        int o = t & 127, pg = t >> 7;
        if (o < 108) {
            float b = b_om[o];
            u64 a01 = pk2(b, b), a23 = pk2(b, b);
            for (int c = 0; c < 64; c++) {
                float wv = wT[c][o];
                u64 w2 = pk2(wv, wv);
                u64 ya = *(const u64*)&y_sT[c][pg*4];
                u64 yb = *(const u64*)&y_sT[c][pg*4+2];
                fma2(a01, ya, w2);
                fma2(a23, yb, w2);
            }
            float v0,v1,v2,v3;
            upk2(a01, v0, v1); upk2(a23, v2, v3);
            om[pg*4+0][o] = v0; om[pg*4+1][o] = v1;
            om[pg*4+2][o] = v2; om[pg*4+3][o] = v3;
        }
    }
    __syncthreads();

    for (int i = t; i < 4096; i += 512) {
        int o = i >> 6, c = i & 63;
        wT[c][o] = out_w[o*64+c];
    }
    if (t < 64) {
        int p = t >> 2, g = t & 3;
        float* m = &om[p][72 + g*9];
        float mx = m[0];
        #pragma unroll
        for (int i = 1; i < 9; i++) mx = fmaxf(mx, m[i]);
        float e[9]; float s = 0.f;
        #pragma unroll
        for (int i = 0; i < 9; i++){ e[i] = expf(m[i]-mx); s += e[i]; }
        float inv = 1.0f/s;
        #pragma unroll
        for (int i = 0; i < 9; i++) m[i] = e[i]*inv;
    }
    __syncthreads();

    {
        int p = t >> 5, l = t & 31;
        int g = l >> 3;
        int wg = w0 + p;
        float v0 = 0.f, v1 = 0.f;
        const float* xb = g_xpad + (size_t)n*HP_*WP_*64 + 2*l;
        #pragma unroll
        for (int pt = 0; pt < 9; pt++) {
            float ox = om[p][(g*9+pt)*2+0];
            float oy = om[p][(g*9+pt)*2+1];
            float mm = om[p][72 + g*9 + pt];
            float fx = (float)(wg + (pt/3)) + ox;
            float fy = (float)(h  + (pt%3)) + oy;
            float fx0 = floorf(fx), fy0 = floorf(fy);
            int ix0 = (int)fx0, iy0 = (int)fy0;
            float wx1 = fx - fx0, wy1 = fy - fy0;
            float wx0 = 1.f - wx1, wy0 = 1.f - wy1;
            #pragma unroll
            for (int cr = 0; cr < 4; cr++) {
                int ix = ix0 + (cr & 1), iy = iy0 + (cr >> 1);
                float wgt = ((cr&1) ? wx1 : wx0) * ((cr>>1) ? wy1 : wy0) * mm;
                if ((unsigned)ix < (unsigned)WP_ && (unsigned)iy < (unsigned)HP_) {
                    float2 xv = *(const float2*)(xb + ((size_t)iy*WP_ + ix)*64);
                    v0 += wgt*xv.x; v1 += wgt*xv.y;
                }
            }
        }
        val_sT[2*l  ][p] = v0;
        val_sT[2*l+1][p] = v1;
    }
    __syncthreads();

    float* ostage = &om[0][0];
    {
        int o = t & 63, pg = t >> 6;
        float b = out_b[o];
        u64 a = pk2(b, b);
        for (int c = 0; c < 64; c++) {
            float wv = wT[c][o];
            u64 w2 = pk2(wv, wv);
            u64 vv = *(const u64*)&val_sT[c][pg*2];
            fma2(a, vv, w2);
        }
        float a0, a1; upk2(a, a0, a1);
        ostage[o*16 + pg*2+0] = siluf_(a0);
        ostage[o*16 + pg*2+1] = siluf_(a1);
    }
    __syncthreads();
    for (int i = t; i < 1024; i += 512) {
        int o = i >> 4, pw = i & 15;
        out[((size_t)(n*64+o)*128 + h)*128 + w0 + pw] = ostage[i];
    }
}

// ================= launch =================
extern "C" void kernel_launch(void* const* d_in, const int* in_sizes, int n_in,
                              void* d_out, int out_size)
{
    const float* input_x = (const float*)d_in[0];
    const float* input_y = (const float*)d_in[1];
    const float* enc_w   = (const float*)d_in[2];
    const float* enc_b   = (const float*)d_in[3];
    const float* bn_g    = (const float*)d_in[4];
    const float* bn_b    = (const float*)d_in[5];
    const float* bn_m    = (const float*)d_in[6];
    const float* bn_v    = (const float*)d_in[7];
    const float* gru_wz  = (const float*)d_in[8];
    const float* gru_bz  = (const float*)d_in[9];
    const float* gru_wr  = (const float*)d_in[10];
    const float* gru_br  = (const float*)d_in[11];
    const float* gru_wq  = (const float*)d_in[12];
    const float* gru_bq  = (const float*)d_in[13];
    const float* dw_w    = (const float*)d_in[14];
    const float* dw_b    = (const float*)d_in[15];
    const float* ln_g    = (const float*)d_in[16];
    const float* ln_b    = (const float*)d_in[17];
    const float* off_w   = (const float*)d_in[18];
    const float* off_b   = (const float*)d_in[19];
    const float* mask_w  = (const float*)d_in[20];
    const float* mask_b  = (const float*)d_in[21];
    const float* inp_w   = (const float*)d_in[22];
    const float* inp_b   = (const float*)d_in[23];
    const float* out_w   = (const float*)d_in[24];
    const float* out_b   = (const float*)d_in[25];

    float* out = (float*)d_out;
    const int OUT1 = N_*C_*HW_;          // 4194304
    const int OUT2 = N_*NET_*HW_;        // 2097152
    float* h_out = (out_size >= OUT1 + OUT2) ? (out + OUT1) : nullptr;

    k_encoder<<<dim3(32,4),   256>>>(input_x, enc_w, enc_b, bn_g, bn_b, bn_m, bn_v);
    k_gru_zr <<<dim3(8,8,4),  256>>>(input_y, gru_wz, gru_wr, gru_bz, gru_br);
    k_gru_q  <<<dim3(8,8,4),  256>>>(input_y, gru_wq, gru_bq, h_out);
    k_inp    <<<dim3(17,4,4), 256>>>(input_x, inp_w, inp_b);
    k_dwln   <<<dim3(8,8,4),  256>>>(dw_w, dw_b, ln_g, ln_b);
    k_dcn    <<<dim3(8,128,4),512>>>(off_w, off_b, mask_w, mask_b, out_w, out_b, out);
}